// round 5
// baseline (speedup 1.0000x reference)
#include <cuda_runtime.h>
#include <math.h>

#define NB 2
#define NF 4096
#define NQ 16384
#define NPTS (NB*NQ)                 // 32768
#define BLOCK 128
#define SPLITS 4
#define TRIS_PER_SPLIT (NF/SPLITS)   // 1024
#define TILE 256

// Scratch (static __device__ arrays: allowed; no allocs anywhere)
__device__ float4 g_tc[NB*NF*4];              // 16 floats per triangle (eval consts)
__device__ float4 g_cr[NB*NF];                // per triangle: centroid.xyz, radius
__device__ int    g_order[NPTS];              // morton-sorted point order per batch
__device__ uint2  g_cand[NPTS*SPLITS];        // per (point,split): top-2 triangle indices

__device__ __forceinline__ float guard_inv(float x) {
    return (fabsf(x) > 1e-12f) ? (1.0f / x) : 1.0f;
}
__device__ __forceinline__ float clamp01(float x) {
    return fminf(fmaxf(x, 0.0f), 1.0f);
}
__device__ __forceinline__ double dclamp01(double x) {
    return fmin(fmax(x, 0.0), 1.0);
}
__device__ __forceinline__ double dsafe_div(double num, double den) {
    double d = (fabs(den) > 1e-12) ? den : 1.0;
    return num / d;
}

// ---------------------------------------------------------------------------
// Kernel 0: per-triangle constants + bounding sphere (centroid, max vtx dist).
// ---------------------------------------------------------------------------
__global__ void k_pre(const float* __restrict__ tris) {
    int i = blockIdx.x * blockDim.x + threadIdx.x;
    if (i >= NB * NF) return;
    const float* t = tris + (size_t)i * 9;
    float ax = t[0], ay = t[1], az = t[2];
    float bx = t[3], by = t[4], bz = t[5];
    float cx = t[6], cy = t[7], cz = t[8];
    float abx = bx - ax, aby = by - ay, abz = bz - az;
    float acx = cx - ax, acy = cy - ay, acz = cz - az;
    float aa = abx*abx + aby*aby + abz*abz;
    float bb = acx*acx + acy*acy + acz*acz;
    float gg = abx*acx + aby*acy + abz*acz;
    float cb2 = aa + bb - 2.0f*gg;
    float den = aa*bb - gg*gg;
    float4* o = g_tc + (size_t)i * 4;
    o[0] = make_float4(ax, ay, az, abx);
    o[1] = make_float4(aby, abz, acx, acy);
    o[2] = make_float4(acz, aa, bb, gg);
    o[3] = make_float4(guard_inv(aa), guard_inv(bb), guard_inv(cb2), guard_inv(den));

    // bounding sphere: centroid + inflated max vertex distance
    float cnx = (ax + bx + cx) * (1.0f/3.0f);
    float cny = (ay + by + cy) * (1.0f/3.0f);
    float cnz = (az + bz + cz) * (1.0f/3.0f);
    float ra = (ax-cnx)*(ax-cnx) + (ay-cny)*(ay-cny) + (az-cnz)*(az-cnz);
    float rb = (bx-cnx)*(bx-cnx) + (by-cny)*(by-cny) + (bz-cnz)*(bz-cnz);
    float rc = (cx-cnx)*(cx-cnx) + (cy-cny)*(cy-cny) + (cz-cnz)*(cz-cnz);
    float r = sqrtf(fmaxf(ra, fmaxf(rb, rc))) * 1.0001f + 1e-6f;
    g_cr[i] = make_float4(cnx, cny, cnz, r);
}

// ---------------------------------------------------------------------------
// Morton helpers + deterministic in-SMEM bitonic sort of points (per batch).
// key = morton18 << 14 | idx  (6 bits/axis; idx in low bits -> total order).
// ---------------------------------------------------------------------------
__device__ __forceinline__ unsigned expand3(unsigned v) {
    v &= 0x3FFu;
    v = (v | (v << 16)) & 0x030000FFu;
    v = (v | (v <<  8)) & 0x0300F00Fu;
    v = (v | (v <<  4)) & 0x030C30C3u;
    v = (v | (v <<  2)) & 0x09249249u;
    return v;
}
__device__ __forceinline__ unsigned q6(float x) {
    int v = (int)((x + 4.0f) * 8.0f);
    return (unsigned)max(0, min(63, v));
}

__global__ void k_sort(const float* __restrict__ pts) {
    extern __shared__ unsigned s[];
    int b = blockIdx.x;
    for (int i = threadIdx.x; i < NQ; i += blockDim.x) {
        const float* p = pts + (size_t)(b * NQ + i) * 3;
        unsigned m = expand3(q6(p[0])) | (expand3(q6(p[1])) << 1) | (expand3(q6(p[2])) << 2);
        s[i] = (m << 14) | (unsigned)i;
    }
    __syncthreads();
    for (unsigned k = 2; k <= (unsigned)NQ; k <<= 1) {
        for (unsigned j = k >> 1; j > 0; j >>= 1) {
            for (unsigned i = threadIdx.x; i < (unsigned)NQ; i += blockDim.x) {
                unsigned ix = i ^ j;
                if (ix > i) {
                    unsigned va = s[i], vb = s[ix];
                    bool up = ((i & k) == 0);
                    if ((va > vb) == up) { s[i] = vb; s[ix] = va; }
                }
            }
            __syncthreads();
        }
    }
    for (int i = threadIdx.x; i < NQ; i += blockDim.x)
        g_order[b * NQ + i] = (int)(s[i] & 0x3FFFu);
}

// ---------------------------------------------------------------------------
// Kernel 1: brute-force scan with warp-uniform sphere pruning.
// Warps hold Morton-adjacent points -> prune test is warp-coherent; skip via
// __any_sync keeps control flow uniform and LDS broadcasts intact.
// Eval body identical to R4 (proven numerics). Top-2 per split.
// ---------------------------------------------------------------------------
__global__ void __launch_bounds__(BLOCK) k_main(const float* __restrict__ points) {
    __shared__ float4 sct[TILE * 4];
    __shared__ float4 scr[TILE];
    int b = blockIdx.z;
    int qpos = blockIdx.x * BLOCK + threadIdx.x;
    int qi = g_order[b * NQ + qpos];
    const float* pp = points + (size_t)(b * NQ + qi) * 3;
    float px = pp[0], py = pp[1], pz = pp[2];
    int triBase = blockIdx.y * TRIS_PER_SPLIT;

    float best  = 3.402823e38f;  int bidx  = triBase;
    float best2 = 3.402823e38f;  int bidx2 = triBase;
    float sb_adj = 3.4e19f;

    for (int tile = 0; tile < TRIS_PER_SPLIT; tile += TILE) {
        __syncthreads();
        {
            const float4* src = g_tc + (size_t)(b * NF + triBase + tile) * 4;
            for (int i = threadIdx.x; i < TILE * 4; i += BLOCK) sct[i] = src[i];
            const float4* srcr = g_cr + (size_t)(b * NF + triBase + tile);
            for (int i = threadIdx.x; i < TILE; i += BLOCK) scr[i] = srcr[i];
        }
        __syncthreads();

        for (int j0 = 0; j0 < TILE; j0 += 16) {
            // refresh prune threshold (stale values are larger -> conservative)
            sb_adj = __fsqrt_rn(best) * 1.0005f + 1e-4f;
            #pragma unroll 4
            for (int j = j0; j < j0 + 16; j++) {
                float4 cr = scr[j];
                float dcx = px - cr.x, dcy = py - cr.y, dcz = pz - cr.z;
                float dc2 = fmaf(dcx, dcx, fmaf(dcy, dcy, dcz * dcz));
                float thr = sb_adj + cr.w;
                bool near_ = dc2 < thr * thr;
                if (!__any_sync(0xFFFFFFFFu, near_)) continue;

                float4 t0 = sct[j*4+0], t1 = sct[j*4+1], t2 = sct[j*4+2], t3 = sct[j*4+3];
                float apx = px - t0.x, apy = py - t0.y, apz = pz - t0.z;
                float abx = t0.w, aby = t1.x, abz = t1.y;
                float acx = t1.z, acy = t1.w, acz = t2.x;
                float aa = t2.y, bb = t2.z, gg = t2.w;

                float d1 = fmaf(abx, apx, fmaf(aby, apy, abz * apz));
                float d2 = fmaf(acx, apx, fmaf(acy, apy, acz * apz));
                float d3 = d1 - aa;
                float d4 = d2 - gg;
                float d5 = d1 - gg;
                float d6 = d2 - bb;

                float vc = fmaf(d1, d4, -d3 * d2);
                float vb = fmaf(d5, d2, -d1 * d6);
                float va = fmaf(d3, d6, -d5 * d4);
                float e1 = d4 - d3;
                float e2 = d5 - d6;

                float v = vb * t3.w;
                float w = vc * t3.w;
                bool mbc = (va <= 0.0f) && (e1 >= 0.0f) && (e2 >= 0.0f);
                float wbc = clamp01(e1 * t3.z);
                v = mbc ? (1.0f - wbc) : v;  w = mbc ? wbc : w;
                bool mac = (vb <= 0.0f) && (d2 >= 0.0f) && (d6 <= 0.0f);
                float wac = clamp01(d2 * t3.y);
                v = mac ? 0.0f : v;  w = mac ? wac : w;
                bool mab = (vc <= 0.0f) && (d1 >= 0.0f) && (d3 <= 0.0f);
                float vab = clamp01(d1 * t3.x);
                v = mab ? vab : v;   w = mab ? 0.0f : w;
                bool mc = (d6 >= 0.0f) && (e2 <= 0.0f);
                v = mc ? 0.0f : v;   w = mc ? 1.0f : w;
                bool mb = (d3 >= 0.0f) && (e1 <= 0.0f);
                v = mb ? 1.0f : v;   w = mb ? 0.0f : w;
                bool ma = (d1 <= 0.0f) && (d2 <= 0.0f);
                v = ma ? 0.0f : v;   w = ma ? 0.0f : w;

                float dx = fmaf(-v, abx, fmaf(-w, acx, apx));
                float dy = fmaf(-v, aby, fmaf(-w, acy, apy));
                float dz = fmaf(-v, abz, fmaf(-w, acz, apz));
                float dist = fmaf(dx, dx, fmaf(dy, dy, dz * dz));

                int t = triBase + tile + j;
                bool lt1 = dist < best;
                bool lt2 = dist < best2;
                best2 = lt1 ? best : (lt2 ? dist : best2);
                bidx2 = lt1 ? bidx : (lt2 ? t    : bidx2);
                best  = lt1 ? dist : best;
                bidx  = lt1 ? t    : bidx;
            }
        }
    }

    g_cand[(size_t)(b * NQ + qi) * SPLITS + blockIdx.y] =
        make_uint2((unsigned)bidx, (unsigned)bidx2);
}

// ---------------------------------------------------------------------------
// Reference formula in DOUBLE precision (true-math ordering for arbitration).
// ---------------------------------------------------------------------------
__device__ void ref_eval_d(const float* __restrict__ tp,
                           double px, double py, double pz,
                           double& d2out, double& rxo, double& ryo, double& rzo) {
    double ax = tp[0], ay = tp[1], az = tp[2];
    double bx = tp[3], by = tp[4], bz = tp[5];
    double cx = tp[6], cy = tp[7], cz = tp[8];

    double abx = bx - ax, aby = by - ay, abz = bz - az;
    double acx = cx - ax, acy = cy - ay, acz = cz - az;
    double apx = px - ax, apy = py - ay, apz = pz - az;
    double d1 = abx*apx + aby*apy + abz*apz;
    double d2 = acx*apx + acy*apy + acz*apz;
    double bpx = px - bx, bpy = py - by, bpz = pz - bz;
    double d3 = abx*bpx + aby*bpy + abz*bpz;
    double d4 = acx*bpx + acy*bpy + acz*bpz;
    double cpx = px - cx, cpy = py - cy, cpz = pz - cz;
    double d5 = abx*cpx + aby*cpy + abz*cpz;
    double d6 = acx*cpx + acy*cpy + acz*cpz;

    double vc = d1*d4 - d3*d2;
    double vb = d5*d2 - d1*d6;
    double va = d3*d6 - d5*d4;
    double v_ab = dclamp01(dsafe_div(d1, d1 - d3));
    double w_ac = dclamp01(dsafe_div(d2, d2 - d6));
    double w_bc = dclamp01(dsafe_div(d4 - d3, (d4 - d3) + (d5 - d6)));
    double denom = va + vb + vc;
    double v = dsafe_div(vb, denom);
    double w = dsafe_div(vc, denom);

    double rx = ax + abx*v + acx*w;
    double ry = ay + aby*v + acy*w;
    double rz = az + abz*v + acz*w;

    bool m_bc = (va <= 0.0) && ((d4 - d3) >= 0.0) && ((d5 - d6) >= 0.0);
    if (m_bc) { rx = bx + w_bc*(cx - bx); ry = by + w_bc*(cy - by); rz = bz + w_bc*(cz - bz); }
    bool m_ac = (vb <= 0.0) && (d2 >= 0.0) && (d6 <= 0.0);
    if (m_ac) { rx = ax + w_ac*acx; ry = ay + w_ac*acy; rz = az + w_ac*acz; }
    bool m_ab = (vc <= 0.0) && (d1 >= 0.0) && (d3 <= 0.0);
    if (m_ab) { rx = ax + v_ab*abx; ry = ay + v_ab*aby; rz = az + v_ab*abz; }
    bool m_c = (d6 >= 0.0) && (d5 <= d6);
    if (m_c) { rx = cx; ry = cy; rz = cz; }
    bool m_b = (d3 >= 0.0) && (d4 <= d3);
    if (m_b) { rx = bx; ry = by; rz = bz; }
    bool m_a = (d1 <= 0.0) && (d2 <= 0.0);
    if (m_a) { rx = ax; ry = ay; rz = az; }

    double dxx = px - rx, dyy = py - ry, dzz = pz - rz;
    d2out = dxx*dxx + dyy*dyy + dzz*dzz;
    rxo = rx; ryo = ry; rzo = rz;
}

// ---------------------------------------------------------------------------
// Kernel 2: arbitrate the <=8 candidates per point in double precision, write
// outputs: dist[32768] | closest[32768*3] | faces[32768] (as float).
// ---------------------------------------------------------------------------
__global__ void k_fin(const float* __restrict__ tris,
                      const float* __restrict__ points,
                      float* __restrict__ out) {
    int i = blockIdx.x * blockDim.x + threadIdx.x;
    if (i >= NPTS) return;
    int b = i / NQ;

    const float* pp = points + (size_t)i * 3;
    double px = pp[0], py = pp[1], pz = pp[2];

    double bestD = 1e300, brx = 0, bry = 0, brz = 0;
    int bestI = 0x7FFFFFFF;

    #pragma unroll
    for (int s = 0; s < SPLITS; s++) {
        uint2 c = g_cand[(size_t)i * SPLITS + s];
        #pragma unroll
        for (int k = 0; k < 2; k++) {
            int idx = (k == 0) ? (int)c.x : (int)c.y;
            const float* tp = tris + (size_t)(b * NF + idx) * 9;
            double d2, rx, ry, rz;
            ref_eval_d(tp, px, py, pz, d2, rx, ry, rz);
            bool take = (d2 < bestD) || (d2 == bestD && idx < bestI);
            if (take) { bestD = d2; bestI = idx; brx = rx; bry = ry; brz = rz; }
        }
    }

    out[i] = (float)bestD;                               // distances [2,16384]
    out[NPTS + (size_t)i*3 + 0] = (float)brx;            // closest_points [2,16384,3]
    out[NPTS + (size_t)i*3 + 1] = (float)bry;
    out[NPTS + (size_t)i*3 + 2] = (float)brz;
    out[(size_t)NPTS*4 + i] = (float)bestI;              // closest_faces [2,16384]
}

extern "C" void kernel_launch(void* const* d_in, const int* in_sizes, int n_in,
                              void* d_out, int out_size) {
    const float* tris = (const float*)d_in[0];   // [2,4096,3,3]
    const float* pts  = (const float*)d_in[1];   // [2,16384,3]
    float* out = (float*)d_out;

    // 64KB dynamic smem for the per-batch bitonic sort (idempotent, not an alloc)
    cudaFuncSetAttribute(k_sort, cudaFuncAttributeMaxDynamicSharedMemorySize, NQ * 4);

    k_pre<<<(NB*NF + 255) / 256, 256>>>(tris);
    k_sort<<<NB, 1024, NQ * 4>>>(pts);
    dim3 grid(NQ / BLOCK, SPLITS, NB);
    k_main<<<grid, BLOCK>>>(pts);
    k_fin<<<(NPTS + 255) / 256, 256>>>(tris, pts, out);
}

// round 6
// speedup vs baseline: 1.7025x; 1.7025x over previous
#include <cuda_runtime.h>
#include <math.h>

#define NB 2
#define NF 4096
#define NQ 16384
#define NPTS (NB*NQ)                 // 32768
#define BLOCK 128
#define SPLITS 4
#define TRIS_PER_SPLIT (NF/SPLITS)   // 1024
#define TILE 256

// Scratch (static __device__ arrays: allowed; no allocs anywhere)
__device__ float4 g_tc[NB*NF*5];              // 20 floats per triangle
__device__ uint2  g_cand[NPTS*SPLITS];        // per (point,split): top-2 triangle indices

__device__ __forceinline__ float guard_inv(float x) {
    return (fabsf(x) > 1e-12f) ? (1.0f / x) : 1.0f;
}
__device__ __forceinline__ float clamp01(float x) {
    return fminf(fmaxf(x, 0.0f), 1.0f);
}
__device__ __forceinline__ double dclamp01(double x) {
    return fmin(fmax(x, 0.0), 1.0);
}
__device__ __forceinline__ double dsafe_div(double num, double den) {
    double d = (fabs(den) > 1e-12) ? den : 1.0;
    return num / d;
}

// ---------------------------------------------------------------------------
// Kernel 0: per-triangle constants.
//  o0 = (ax, ay, az, abx)   o1 = (aby, abz, acx, acy)
//  o2 = (acz, aa, bb, gg)   o3 = (inv_aa, inv_bb, inv_cb2, inv_den)
//  o4 = (cb2, aa-gg, den, 0)
// ---------------------------------------------------------------------------
__global__ void k_pre(const float* __restrict__ tris) {
    int i = blockIdx.x * blockDim.x + threadIdx.x;
    if (i >= NB * NF) return;
    const float* t = tris + (size_t)i * 9;
    float ax = t[0], ay = t[1], az = t[2];
    float bx = t[3], by = t[4], bz = t[5];
    float cx = t[6], cy = t[7], cz = t[8];
    float abx = bx - ax, aby = by - ay, abz = bz - az;
    float acx = cx - ax, acy = cy - ay, acz = cz - az;
    float aa = abx*abx + aby*aby + abz*abz;
    float bb = acx*acx + acy*acy + acz*acz;
    float gg = abx*acx + aby*acy + abz*acz;
    float cb2 = aa + bb - 2.0f*gg;               // |c-b|^2
    float den = aa*bb - gg*gg;                   // va+vb+vc
    float4* o = g_tc + (size_t)i * 5;
    o[0] = make_float4(ax, ay, az, abx);
    o[1] = make_float4(aby, abz, acx, acy);
    o[2] = make_float4(acz, aa, bb, gg);
    o[3] = make_float4(guard_inv(aa), guard_inv(bb), guard_inv(cb2), guard_inv(den));
    o[4] = make_float4(cb2, aa - gg, den, 0.0f);
}

// ---------------------------------------------------------------------------
// Kernel 1: brute-force scan. 1 point/thread; triangles split over blockIdx.y.
// Region logic = inside-test + min-of-3-clamped-edges (scalar dists pick the
// edge only); FINAL distance is vector-form (proven tight ordering). Top-2
// per split; f64 arbitration downstream absorbs near-tie selection noise.
// ---------------------------------------------------------------------------
__global__ void __launch_bounds__(BLOCK) k_main(const float* __restrict__ points) {
    __shared__ float4 sh[TILE * 5];
    int b = blockIdx.z;
    int q = blockIdx.x * BLOCK + threadIdx.x;
    const float* pp = points + (size_t)(b * NQ + q) * 3;
    float px = pp[0], py = pp[1], pz = pp[2];
    int triBase = blockIdx.y * TRIS_PER_SPLIT;

    float best  = 3.402823e38f;  int bidx  = triBase;
    float best2 = 3.402823e38f;  int bidx2 = triBase;

    for (int tile = 0; tile < TRIS_PER_SPLIT; tile += TILE) {
        __syncthreads();
        const float4* src = g_tc + (size_t)(b * NF + triBase + tile) * 5;
        for (int i = threadIdx.x; i < TILE * 5; i += BLOCK) sh[i] = src[i];
        __syncthreads();

        #pragma unroll 8
        for (int j = 0; j < TILE; j++) {
            float4 t0 = sh[j*5+0], t1 = sh[j*5+1], t2 = sh[j*5+2];
            float4 t3 = sh[j*5+3], t4 = sh[j*5+4];
            float apx = px - t0.x, apy = py - t0.y, apz = pz - t0.z;
            float abx = t0.w, aby = t1.x, abz = t1.y;
            float acx = t1.z, acy = t1.w, acz = t2.x;
            float aa = t2.y, bb = t2.z, gg = t2.w;
            float cb2 = t4.x, amg = t4.y, den = t4.z;

            float d1  = fmaf(abx, apx, fmaf(aby, apy, abz * apz));
            float d2  = fmaf(acx, apx, fmaf(acy, apy, acz * apz));
            float app = fmaf(apx, apx, fmaf(apy, apy, apz * apz));

            // barycentric numerators (algebraically == reference's vb, vc, va)
            float vc = fmaf(aa, d2, -(gg * d1));
            float vb = fmaf(bb, d1, -(gg * d2));
            float va = den - vb - vc;
            bool inside = (vb >= 0.0f) && (vc >= 0.0f) && (va >= 0.0f);

            // clamped edge parameters
            float t_ab = clamp01(d1 * t3.x);
            float t_ac = clamp01(d2 * t3.y);
            float e1   = (d2 - d1) + amg;          // bp.(c-b)
            float t_bc = clamp01(e1 * t3.z);

            // scalar edge distances (SELECTION ONLY — never emitted)
            float d1_2 = d1 + d1;
            float dab = fmaf(t_ab, fmaf(t_ab, aa,  -d1_2),     app);
            float dac = fmaf(t_ac, fmaf(t_ac, bb,  -(d2+d2)),  app);
            float bp2 = (app + aa) - d1_2;
            float dbc = fmaf(t_bc, fmaf(t_bc, cb2, -(e1+e1)),  bp2);

            // pick edge, then interior override
            bool pab = dab <= dac;
            float ve = pab ? t_ab : 0.0f;
            float we = pab ? 0.0f : t_ac;
            float de = fminf(dab, dac);
            bool pbc = de <= dbc;
            ve = pbc ? ve : (1.0f - t_bc);
            we = pbc ? we : t_bc;
            float v = inside ? (vb * t3.w) : ve;
            float w = inside ? (vc * t3.w) : we;

            // vector-form distance (small residuals -> ~1e-9 ordering noise)
            float dx = fmaf(-v, abx, fmaf(-w, acx, apx));
            float dy = fmaf(-v, aby, fmaf(-w, acy, apy));
            float dz = fmaf(-v, abz, fmaf(-w, acz, apz));
            float dist = fmaf(dx, dx, fmaf(dy, dy, dz * dz));

            int t = triBase + tile + j;
            bool lt1 = dist < best;
            bool lt2 = dist < best2;
            best2 = lt1 ? best : (lt2 ? dist : best2);
            bidx2 = lt1 ? bidx : (lt2 ? t    : bidx2);
            best  = lt1 ? dist : best;
            bidx  = lt1 ? t    : bidx;
        }
    }

    g_cand[(size_t)(b * NQ + q) * SPLITS + blockIdx.y] =
        make_uint2((unsigned)bidx, (unsigned)bidx2);
}

// ---------------------------------------------------------------------------
// Reference formula in DOUBLE precision (true-math ordering for arbitration).
// ---------------------------------------------------------------------------
__device__ void ref_eval_d(const float* __restrict__ tp,
                           double px, double py, double pz,
                           double& d2out, double& rxo, double& ryo, double& rzo) {
    double ax = tp[0], ay = tp[1], az = tp[2];
    double bx = tp[3], by = tp[4], bz = tp[5];
    double cx = tp[6], cy = tp[7], cz = tp[8];

    double abx = bx - ax, aby = by - ay, abz = bz - az;
    double acx = cx - ax, acy = cy - ay, acz = cz - az;
    double apx = px - ax, apy = py - ay, apz = pz - az;
    double d1 = abx*apx + aby*apy + abz*apz;
    double d2 = acx*apx + acy*apy + acz*apz;
    double bpx = px - bx, bpy = py - by, bpz = pz - bz;
    double d3 = abx*bpx + aby*bpy + abz*bpz;
    double d4 = acx*bpx + acy*bpy + acz*bpz;
    double cpx = px - cx, cpy = py - cy, cpz = pz - cz;
    double d5 = abx*cpx + aby*cpy + abz*cpz;
    double d6 = acx*cpx + acy*cpy + acz*cpz;

    double vc = d1*d4 - d3*d2;
    double vb = d5*d2 - d1*d6;
    double va = d3*d6 - d5*d4;
    double v_ab = dclamp01(dsafe_div(d1, d1 - d3));
    double w_ac = dclamp01(dsafe_div(d2, d2 - d6));
    double w_bc = dclamp01(dsafe_div(d4 - d3, (d4 - d3) + (d5 - d6)));
    double denom = va + vb + vc;
    double v = dsafe_div(vb, denom);
    double w = dsafe_div(vc, denom);

    double rx = ax + abx*v + acx*w;
    double ry = ay + aby*v + acy*w;
    double rz = az + abz*v + acz*w;

    bool m_bc = (va <= 0.0) && ((d4 - d3) >= 0.0) && ((d5 - d6) >= 0.0);
    if (m_bc) { rx = bx + w_bc*(cx - bx); ry = by + w_bc*(cy - by); rz = bz + w_bc*(cz - bz); }
    bool m_ac = (vb <= 0.0) && (d2 >= 0.0) && (d6 <= 0.0);
    if (m_ac) { rx = ax + w_ac*acx; ry = ay + w_ac*acy; rz = az + w_ac*acz; }
    bool m_ab = (vc <= 0.0) && (d1 >= 0.0) && (d3 <= 0.0);
    if (m_ab) { rx = ax + v_ab*abx; ry = ay + v_ab*aby; rz = az + v_ab*abz; }
    bool m_c = (d6 >= 0.0) && (d5 <= d6);
    if (m_c) { rx = cx; ry = cy; rz = cz; }
    bool m_b = (d3 >= 0.0) && (d4 <= d3);
    if (m_b) { rx = bx; ry = by; rz = bz; }
    bool m_a = (d1 <= 0.0) && (d2 <= 0.0);
    if (m_a) { rx = ax; ry = ay; rz = az; }

    double dxx = px - rx, dyy = py - ry, dzz = pz - rz;
    d2out = dxx*dxx + dyy*dyy + dzz*dzz;
    rxo = rx; ryo = ry; rzo = rz;
}

// ---------------------------------------------------------------------------
// Kernel 2: arbitrate the <=8 candidates per point in double precision, write
// outputs: dist[32768] | closest[32768*3] | faces[32768] (as float).
// ---------------------------------------------------------------------------
__global__ void k_fin(const float* __restrict__ tris,
                      const float* __restrict__ points,
                      float* __restrict__ out) {
    int i = blockIdx.x * blockDim.x + threadIdx.x;
    if (i >= NPTS) return;
    int b = i / NQ;

    const float* pp = points + (size_t)i * 3;
    double px = pp[0], py = pp[1], pz = pp[2];

    double bestD = 1e300, brx = 0, bry = 0, brz = 0;
    int bestI = 0x7FFFFFFF;

    #pragma unroll
    for (int s = 0; s < SPLITS; s++) {
        uint2 c = g_cand[(size_t)i * SPLITS + s];
        #pragma unroll
        for (int k = 0; k < 2; k++) {
            int idx = (k == 0) ? (int)c.x : (int)c.y;
            const float* tp = tris + (size_t)(b * NF + idx) * 9;
            double d2, rx, ry, rz;
            ref_eval_d(tp, px, py, pz, d2, rx, ry, rz);
            bool take = (d2 < bestD) || (d2 == bestD && idx < bestI);
            if (take) { bestD = d2; bestI = idx; brx = rx; bry = ry; brz = rz; }
        }
    }

    out[i] = (float)bestD;                               // distances [2,16384]
    out[NPTS + (size_t)i*3 + 0] = (float)brx;            // closest_points [2,16384,3]
    out[NPTS + (size_t)i*3 + 1] = (float)bry;
    out[NPTS + (size_t)i*3 + 2] = (float)brz;
    out[(size_t)NPTS*4 + i] = (float)bestI;              // closest_faces [2,16384]
}

extern "C" void kernel_launch(void* const* d_in, const int* in_sizes, int n_in,
                              void* d_out, int out_size) {
    const float* tris = (const float*)d_in[0];   // [2,4096,3,3]
    const float* pts  = (const float*)d_in[1];   // [2,16384,3]
    float* out = (float*)d_out;

    k_pre<<<(NB*NF + 255) / 256, 256>>>(tris);
    dim3 grid(NQ / BLOCK, SPLITS, NB);
    k_main<<<grid, BLOCK>>>(pts);
    k_fin<<<(NPTS + 255) / 256, 256>>>(tris, pts, out);
}

// round 7
// speedup vs baseline: 1.7481x; 1.0268x over previous
#include <cuda_runtime.h>
#include <math.h>

#define NB 2
#define NF 4096
#define NQ 16384
#define NPTS (NB*NQ)                  // 32768
#define BLOCK 128
#define SPLITS 4
#define TRIS_PER_SPLIT (NF/SPLITS)    // 1024
#define PAIRS_PER_SPLIT (TRIS_PER_SPLIT/2)  // 512
#define TILE_PAIRS 128                // 256 triangles per smem tile, 20KB

typedef unsigned long long u64;

// Scratch (static __device__ arrays: allowed; no allocs anywhere)
__device__ float4 g_tc2[NB*(NF/2)*10];   // pair-interleaved consts: 10 x float4 per tri-pair
__device__ uint2  g_cand[NPTS*SPLITS];   // per (point,split): top-2 triangle indices

// ---- f32x2 packed helpers (sm_100a) ----
__device__ __forceinline__ u64 f2pack(float lo, float hi) {
    u64 r; asm("mov.b64 %0, {%1, %2};" : "=l"(r) : "f"(lo), "f"(hi)); return r;
}
__device__ __forceinline__ void f2unpack(u64 v, float& lo, float& hi) {
    asm("mov.b64 {%0, %1}, %2;" : "=f"(lo), "=f"(hi) : "l"(v));
}
__device__ __forceinline__ u64 f2add(u64 a, u64 b) {
    u64 r; asm("add.rn.f32x2 %0, %1, %2;" : "=l"(r) : "l"(a), "l"(b)); return r;
}
__device__ __forceinline__ u64 f2mul(u64 a, u64 b) {
    u64 r; asm("mul.rn.f32x2 %0, %1, %2;" : "=l"(r) : "l"(a), "l"(b)); return r;
}
__device__ __forceinline__ u64 f2fma(u64 a, u64 b, u64 c) {
    u64 r; asm("fma.rn.f32x2 %0, %1, %2, %3;" : "=l"(r) : "l"(a), "l"(b), "l"(c)); return r;
}

__device__ __forceinline__ float guard_inv(float x) {
    return (fabsf(x) > 1e-12f) ? (1.0f / x) : 1.0f;
}
__device__ __forceinline__ double dclamp01(double x) {
    return fmin(fmax(x, 0.0), 1.0);
}
__device__ __forceinline__ double dsafe_div(double num, double den) {
    double d = (fabs(den) > 1e-12) ? den : 1.0;
    return num / d;
}

// ---------------------------------------------------------------------------
// Kernel 0: per-triangle constants, pair-interleaved + pre-negated.
// Slots (each stored as {even_tri, odd_tri} float pair):
//  0:-ax 1:-ay 2:-az 3:abx 4:aby 5:abz 6:acx 7:acy 8:acz 9:aa
// 10:bb 11:-gg 12:-1/aa 13:-1/bb 14:-1/cb2 15:-1/den 16:aa-gg 17:cb2 18:den 19:pad
// ---------------------------------------------------------------------------
__global__ void k_pre(const float* __restrict__ tris) {
    int i = blockIdx.x * blockDim.x + threadIdx.x;
    if (i >= NB * NF) return;
    const float* t = tris + (size_t)i * 9;
    float ax = t[0], ay = t[1], az = t[2];
    float bx = t[3], by = t[4], bz = t[5];
    float cx = t[6], cy = t[7], cz = t[8];
    float abx = bx - ax, aby = by - ay, abz = bz - az;
    float acx = cx - ax, acy = cy - ay, acz = cz - az;
    float aa = abx*abx + aby*aby + abz*abz;
    float bb = acx*acx + acy*acy + acz*acz;
    float gg = abx*acx + aby*acy + abz*acz;
    float cb2 = aa + bb - 2.0f*gg;
    float den = aa*bb - gg*gg;

    int pi = i >> 1, lane = i & 1;
    float* o = ((float*)g_tc2) + (size_t)pi * 40 + lane;
    o[ 0] = -ax;  o[ 2] = -ay;  o[ 4] = -az;
    o[ 6] = abx;  o[ 8] = aby;  o[10] = abz;
    o[12] = acx;  o[14] = acy;  o[16] = acz;
    o[18] = aa;   o[20] = bb;   o[22] = -gg;
    o[24] = -guard_inv(aa);  o[26] = -guard_inv(bb);
    o[28] = -guard_inv(cb2); o[30] = -guard_inv(den);
    o[32] = aa - gg; o[34] = cb2; o[36] = den; o[38] = 0.0f;
}

// per-lane edge/interior selection -> NEGATED (v,w)
__device__ __forceinline__ void lane_sel(
    float vb, float vc, float vbc, float den,
    float dab, float dac, float dbc,
    float nta, float ntb, float ntc,
    float nvi, float nwi, float& nv, float& nw)
{
    bool inside = (vb >= 0.0f) && (vc >= 0.0f) && (vbc <= den);
    bool pab = dab <= dac;
    float nve = pab ? nta : 0.0f;
    float nwe = pab ? 0.0f : ntb;
    float de = fminf(dab, dac);
    bool pbc = de <= dbc;
    float nvbc = -ntc - 1.0f;            // = -(1 - t_bc)
    nve = pbc ? nve : nvbc;
    nwe = pbc ? nwe : ntc;
    nv = inside ? nvi : nve;
    nw = inside ? nwi : nwe;
}

__device__ __forceinline__ void top2_upd(
    float dist, int t, float& best, int& bidx, float& best2, int& bidx2)
{
    bool lt1 = dist < best;
    bool lt2 = dist < best2;
    best2 = lt1 ? best : (lt2 ? dist : best2);
    bidx2 = lt1 ? bidx : (lt2 ? t    : bidx2);
    best  = lt1 ? dist : best;
    bidx  = lt1 ? t    : bidx;
}

// ---------------------------------------------------------------------------
// Kernel 1: brute-force scan, 2 triangles per iteration packed in f32x2 lanes.
// Packed math is bitwise-identical to R6's scalar pipeline (negations exact);
// scalar region-selection per lane; top-2 per split; f64 arbitration after.
// ---------------------------------------------------------------------------
__global__ void __launch_bounds__(BLOCK, 7) k_main(const float* __restrict__ points) {
    __shared__ ulonglong2 sh[TILE_PAIRS * 10];
    int b = blockIdx.z;
    int q = blockIdx.x * BLOCK + threadIdx.x;
    const float* pp = points + (size_t)(b * NQ + q) * 3;
    float px = pp[0], py = pp[1], pz = pp[2];
    u64 PX = f2pack(px, px), PY = f2pack(py, py), PZ = f2pack(pz, pz);
    int pairBase = blockIdx.y * PAIRS_PER_SPLIT;

    float best  = 3.402823e38f;  int bidx  = pairBase * 2;
    float best2 = 3.402823e38f;  int bidx2 = pairBase * 2;

    for (int tp0 = 0; tp0 < PAIRS_PER_SPLIT; tp0 += TILE_PAIRS) {
        __syncthreads();
        {
            const float4* src = g_tc2 + (size_t)(b * (NF/2) + pairBase + tp0) * 10;
            float4* dst = (float4*)sh;
            #pragma unroll
            for (int i = threadIdx.x; i < TILE_PAIRS * 10; i += BLOCK) dst[i] = src[i];
        }
        __syncthreads();

        #pragma unroll 4
        for (int j = 0; j < TILE_PAIRS; j++) {
            const ulonglong2* tp = sh + j * 10;
            ulonglong2 s0 = tp[0], s1 = tp[1], s2 = tp[2], s3 = tp[3], s4 = tp[4];
            ulonglong2 s5 = tp[5], s6 = tp[6], s7 = tp[7], s8 = tp[8], s9 = tp[9];
            u64 NAX = s0.x, NAY = s0.y, NAZ = s1.x, ABX = s1.y;
            u64 ABY = s2.x, ABZ = s2.y, ACX = s3.x, ACY = s3.y;
            u64 ACZ = s4.x, AA  = s4.y, BB  = s5.x, NGG = s5.y;
            u64 NIA = s6.x, NIB = s6.y, NIC = s7.x, NID = s7.y;
            u64 AMG = s8.x, CB2 = s8.y, DEN = s9.x;

            u64 APX = f2add(PX, NAX);
            u64 APY = f2add(PY, NAY);
            u64 APZ = f2add(PZ, NAZ);

            u64 D1  = f2fma(ABX, APX, f2fma(ABY, APY, f2mul(ABZ, APZ)));
            u64 D2  = f2fma(ACX, APX, f2fma(ACY, APY, f2mul(ACZ, APZ)));
            u64 APP = f2fma(APX, APX, f2fma(APY, APY, f2mul(APZ, APZ)));

            u64 VC  = f2fma(AA, D2, f2mul(NGG, D1));
            u64 VB  = f2fma(BB, D1, f2mul(NGG, D2));
            u64 VBC = f2add(VB, VC);

            // negated clamped edge params
            u64 NTAr = f2mul(D1, NIA);
            u64 NTBr = f2mul(D2, NIB);
            u64 ND1  = f2mul(D1, f2pack(-1.0f, -1.0f));
            u64 E1   = f2add(f2add(D2, ND1), AMG);
            u64 NTCr = f2mul(E1, NIC);
            float nta0, nta1, ntb0, ntb1, ntc0, ntc1;
            f2unpack(NTAr, nta0, nta1);
            f2unpack(NTBr, ntb0, ntb1);
            f2unpack(NTCr, ntc0, ntc1);
            nta0 = fmaxf(fminf(nta0, 0.0f), -1.0f);
            nta1 = fmaxf(fminf(nta1, 0.0f), -1.0f);
            ntb0 = fmaxf(fminf(ntb0, 0.0f), -1.0f);
            ntb1 = fmaxf(fminf(ntb1, 0.0f), -1.0f);
            ntc0 = fmaxf(fminf(ntc0, 0.0f), -1.0f);
            ntc1 = fmaxf(fminf(ntc1, 0.0f), -1.0f);
            u64 NTA = f2pack(nta0, nta1);
            u64 NTB = f2pack(ntb0, ntb1);
            u64 NTC = f2pack(ntc0, ntc1);

            // scalar edge distances (selection only), packed arithmetic
            u64 D1_2  = f2add(D1, D1);
            u64 ND1_2 = f2add(ND1, ND1);
            u64 DAB = f2fma(NTA, f2fma(NTA, AA, D1_2), APP);
            u64 D2_2  = f2add(D2, D2);
            u64 DAC = f2fma(NTB, f2fma(NTB, BB, D2_2), APP);
            u64 BP2 = f2add(f2add(APP, AA), ND1_2);
            u64 E1_2 = f2add(E1, E1);
            u64 DBC = f2fma(NTC, f2fma(NTC, CB2, E1_2), BP2);

            u64 NVI = f2mul(VB, NID);
            u64 NWI = f2mul(VC, NID);

            float vb0, vb1, vc0, vc1, vbc0, vbc1, den0, den1;
            float dab0, dab1, dac0, dac1, dbc0, dbc1, nvi0, nvi1, nwi0, nwi1;
            f2unpack(VB, vb0, vb1);   f2unpack(VC, vc0, vc1);
            f2unpack(VBC, vbc0, vbc1); f2unpack(DEN, den0, den1);
            f2unpack(DAB, dab0, dab1); f2unpack(DAC, dac0, dac1);
            f2unpack(DBC, dbc0, dbc1);
            f2unpack(NVI, nvi0, nvi1); f2unpack(NWI, nwi0, nwi1);

            float nv0, nw0, nv1, nw1;
            lane_sel(vb0, vc0, vbc0, den0, dab0, dac0, dbc0, nta0, ntb0, ntc0, nvi0, nwi0, nv0, nw0);
            lane_sel(vb1, vc1, vbc1, den1, dab1, dac1, dbc1, nta1, ntb1, ntc1, nvi1, nwi1, nv1, nw1);
            u64 NV = f2pack(nv0, nv1);
            u64 NW = f2pack(nw0, nw1);

            // vector-form distance (tight ordering; bitwise == R6 per lane)
            u64 DX = f2fma(NV, ABX, f2fma(NW, ACX, APX));
            u64 DY = f2fma(NV, ABY, f2fma(NW, ACY, APY));
            u64 DZ = f2fma(NV, ABZ, f2fma(NW, ACZ, APZ));
            u64 DIST = f2fma(DX, DX, f2fma(DY, DY, f2mul(DZ, DZ)));
            float dist0, dist1;
            f2unpack(DIST, dist0, dist1);

            int te = (pairBase + tp0 + j) * 2;
            top2_upd(dist0, te,     best, bidx, best2, bidx2);
            top2_upd(dist1, te + 1, best, bidx, best2, bidx2);
        }
    }

    g_cand[(size_t)(b * NQ + q) * SPLITS + blockIdx.y] =
        make_uint2((unsigned)bidx, (unsigned)bidx2);
}

// ---------------------------------------------------------------------------
// Reference formula in DOUBLE precision (true-math ordering for arbitration).
// ---------------------------------------------------------------------------
__device__ void ref_eval_d(const float* __restrict__ tp,
                           double px, double py, double pz,
                           double& d2out, double& rxo, double& ryo, double& rzo) {
    double ax = tp[0], ay = tp[1], az = tp[2];
    double bx = tp[3], by = tp[4], bz = tp[5];
    double cx = tp[6], cy = tp[7], cz = tp[8];

    double abx = bx - ax, aby = by - ay, abz = bz - az;
    double acx = cx - ax, acy = cy - ay, acz = cz - az;
    double apx = px - ax, apy = py - ay, apz = pz - az;
    double d1 = abx*apx + aby*apy + abz*apz;
    double d2 = acx*apx + acy*apy + acz*apz;
    double bpx = px - bx, bpy = py - by, bpz = pz - bz;
    double d3 = abx*bpx + aby*bpy + abz*bpz;
    double d4 = acx*bpx + acy*bpy + acz*bpz;
    double cpx = px - cx, cpy = py - cy, cpz = pz - cz;
    double d5 = abx*cpx + aby*cpy + abz*cpz;
    double d6 = acx*cpx + acy*cpy + acz*cpz;

    double vc = d1*d4 - d3*d2;
    double vb = d5*d2 - d1*d6;
    double va = d3*d6 - d5*d4;
    double v_ab = dclamp01(dsafe_div(d1, d1 - d3));
    double w_ac = dclamp01(dsafe_div(d2, d2 - d6));
    double w_bc = dclamp01(dsafe_div(d4 - d3, (d4 - d3) + (d5 - d6)));
    double denom = va + vb + vc;
    double v = dsafe_div(vb, denom);
    double w = dsafe_div(vc, denom);

    double rx = ax + abx*v + acx*w;
    double ry = ay + aby*v + acy*w;
    double rz = az + abz*v + acz*w;

    bool m_bc = (va <= 0.0) && ((d4 - d3) >= 0.0) && ((d5 - d6) >= 0.0);
    if (m_bc) { rx = bx + w_bc*(cx - bx); ry = by + w_bc*(cy - by); rz = bz + w_bc*(cz - bz); }
    bool m_ac = (vb <= 0.0) && (d2 >= 0.0) && (d6 <= 0.0);
    if (m_ac) { rx = ax + w_ac*acx; ry = ay + w_ac*acy; rz = az + w_ac*acz; }
    bool m_ab = (vc <= 0.0) && (d1 >= 0.0) && (d3 <= 0.0);
    if (m_ab) { rx = ax + v_ab*abx; ry = ay + v_ab*aby; rz = az + v_ab*abz; }
    bool m_c = (d6 >= 0.0) && (d5 <= d6);
    if (m_c) { rx = cx; ry = cy; rz = cz; }
    bool m_b = (d3 >= 0.0) && (d4 <= d3);
    if (m_b) { rx = bx; ry = by; rz = bz; }
    bool m_a = (d1 <= 0.0) && (d2 <= 0.0);
    if (m_a) { rx = ax; ry = ay; rz = az; }

    double dxx = px - rx, dyy = py - ry, dzz = pz - rz;
    d2out = dxx*dxx + dyy*dyy + dzz*dzz;
    rxo = rx; ryo = ry; rzo = rz;
}

// ---------------------------------------------------------------------------
// Kernel 2: arbitrate the <=8 candidates per point in double precision, write
// outputs: dist[32768] | closest[32768*3] | faces[32768] (as float).
// ---------------------------------------------------------------------------
__global__ void k_fin(const float* __restrict__ tris,
                      const float* __restrict__ points,
                      float* __restrict__ out) {
    int i = blockIdx.x * blockDim.x + threadIdx.x;
    if (i >= NPTS) return;
    int b = i / NQ;

    const float* pp = points + (size_t)i * 3;
    double px = pp[0], py = pp[1], pz = pp[2];

    double bestD = 1e300, brx = 0, bry = 0, brz = 0;
    int bestI = 0x7FFFFFFF;

    #pragma unroll
    for (int s = 0; s < SPLITS; s++) {
        uint2 c = g_cand[(size_t)i * SPLITS + s];
        #pragma unroll
        for (int k = 0; k < 2; k++) {
            int idx = (k == 0) ? (int)c.x : (int)c.y;
            const float* tp = tris + (size_t)(b * NF + idx) * 9;
            double d2, rx, ry, rz;
            ref_eval_d(tp, px, py, pz, d2, rx, ry, rz);
            bool take = (d2 < bestD) || (d2 == bestD && idx < bestI);
            if (take) { bestD = d2; bestI = idx; brx = rx; bry = ry; brz = rz; }
        }
    }

    out[i] = (float)bestD;                               // distances [2,16384]
    out[NPTS + (size_t)i*3 + 0] = (float)brx;            // closest_points [2,16384,3]
    out[NPTS + (size_t)i*3 + 1] = (float)bry;
    out[NPTS + (size_t)i*3 + 2] = (float)brz;
    out[(size_t)NPTS*4 + i] = (float)bestI;              // closest_faces [2,16384]
}

extern "C" void kernel_launch(void* const* d_in, const int* in_sizes, int n_in,
                              void* d_out, int out_size) {
    const float* tris = (const float*)d_in[0];   // [2,4096,3,3]
    const float* pts  = (const float*)d_in[1];   // [2,16384,3]
    float* out = (float*)d_out;

    k_pre<<<(NB*NF + 255) / 256, 256>>>(tris);
    dim3 grid(NQ / BLOCK, SPLITS, NB);
    k_main<<<grid, BLOCK>>>(pts);
    k_fin<<<(NPTS + 255) / 256, 256>>>(tris, pts, out);
}